// round 13
// baseline (speedup 1.0000x reference)
#include <cuda_runtime.h>
#include <cstdint>
#include <cstddef>

// Reverse LSTM: B=128, T=2048, H=512.  out[b,t,:] = h_t (consumes x[b, T-1-t]).
//
// R12: dual-chain latency hiding. 128 CTAs = 2 pairs x 64 col-groups; each CTA
// owns 32 z-cols (8 h-cols x 4 gates, Wh slice 64KB SMEM) and interleaves TWO
// independent batch-group chains (bgA = 2p, bgB = 2p+1, 32 rows each). Each
// chain's exchange round-trip (release -> poll -> 64KB TMA) is issued at the
// end of its phase and completes during the other chain's phase, removing the
// ~10k-cycle exposed step-boundary latency that bound R2-R11 at ~20ms.

#define TT   2048
#define HID  512
#define FPAD 32              // flag padding (uints) -> 128B per flag
#define ZPAD 36              // z2 row pad: gate reads bank-conflict-free, even

__device__ float    g_Hbuf[4][2][HID * 32];    // [bg][parity][k*32 + b] k-major
__device__ unsigned g_flag[4][64][FPAD];       // [bg][cg6][0], padded

typedef unsigned long long u64;

__device__ __forceinline__ void ffma2(u64 &d, u64 a, u64 b) {
    asm volatile("fma.rn.f32x2 %0, %1, %2, %0;" : "+l"(d) : "l"(a), "l"(b));
}
__device__ __forceinline__ u64 pack2(float x) {
    u64 r; asm("mov.b64 %0, {%1, %1};" : "=l"(r) : "f"(x)); return r;
}
__device__ __forceinline__ void poll_flag(const unsigned* f, unsigned tgt) {
    unsigned v;
    do {
        asm volatile("ld.acquire.gpu.global.u32 %0, [%1];"
                     : "=r"(v) : "l"(f) : "memory");
    } while (v < tgt);
}
__device__ __forceinline__ void bulk_g2s(unsigned dst_smem, const void* src,
                                         unsigned bytes, unsigned mbar) {
    asm volatile(
        "cp.async.bulk.shared::cluster.global.mbarrier::complete_tx::bytes "
        "[%0], [%1], %2, [%3];"
        :: "r"(dst_smem), "l"(src), "r"(bytes), "r"(mbar) : "memory");
}
__device__ __forceinline__ void mbar_init(unsigned mbar, unsigned cnt) {
    asm volatile("mbarrier.init.shared.b64 [%0], %1;" :: "r"(mbar), "r"(cnt) : "memory");
}
__device__ __forceinline__ void mbar_expect_tx(unsigned mbar, unsigned bytes) {
    asm volatile("mbarrier.arrive.expect_tx.shared.b64 _, [%0], %1;"
                 :: "r"(mbar), "r"(bytes) : "memory");
}
__device__ __forceinline__ void mbar_wait(unsigned mbar, unsigned parity) {
    unsigned done;
    asm volatile(
        "{\n\t.reg .pred p;\n\t"
        "mbarrier.try_wait.parity.acquire.cta.shared::cta.b64 p, [%1], %2;\n\t"
        "selp.b32 %0, 1, 0, p;\n\t}"
        : "=r"(done) : "r"(mbar), "r"(parity) : "memory");
    if (!done) {
        asm volatile(
            "{\n\t.reg .pred P1;\n\t"
            "WL_%=:\n\t"
            "mbarrier.try_wait.parity.acquire.cta.shared::cta.b64 P1, [%0], %1, 0x989680;\n\t"
            "@P1 bra.uni WD_%=;\n\t"
            "bra.uni WL_%=;\n\t"
            "WD_%=:\n\t}"
            :: "r"(mbar), "r"(parity) : "memory");
    }
}

__global__ void lstm_init_kernel() {
    int i = threadIdx.x;                // 256 = 4*64 flags
    g_flag[i >> 6][i & 63][0] = 0u;
}

extern __shared__ float sm[];

__global__ void __launch_bounds__(256, 1)
lstm_persistent_kernel(const float* __restrict__ x,
                       const float* __restrict__ Wi,
                       const float* __restrict__ Wh,
                       const float* __restrict__ bias,
                       float* __restrict__ out)
{
    // SMEM (floats):
    //  Wh_s [k=512][c=32]   @ 0       (65536 B)   c = g*8 + jj
    //  hA_s [k=512][b=32]   @ 16384   (65536 B)
    //  hB_s [k=512][b=32]   @ 32768   (65536 B)
    //  z2   [kh=2][c=32][ZPAD] @ 49152 (9216 B)
    //  xA[32], xB[32]       @ 51456
    //  mbar u64 x2          @ 51520   (16B aligned)   total 206,096 B
    float* Wh_s = sm;
    float* hA_s = sm + 16384;
    float* hB_s = sm + 32768;
    float* z2   = sm + 49152;
    float* xA_s = sm + 51456;
    float* xB_s = sm + 51488;

    const int tid = threadIdx.x;
    const int p   = blockIdx.x >> 6;     // pair 0..1
    const int cg6 = blockIdx.x & 63;     // 0..63 -> h-cols cg6*8..cg6*8+7
    const int bgA = p * 2;
    const int bgB = p * 2 + 1;

    const int wid  = tid >> 5;           // 0..7
    const int kh   = wid >> 2;           // k-half
    const int oct  = wid & 3;            // batch octet
    const int lane = tid & 31;
    const int c2   = lane & 15;          // col pair (cols 2c2, 2c2+1)
    const int bh   = lane >> 4;          // batch nibble within octet

    const int j = tid & 7;               // gate-phase h-col
    const int b = tid >> 3;              // gate-phase batch row (0..31)

    const unsigned smem_base = (unsigned)__cvta_generic_to_shared(sm);
    const unsigned hA_smem   = smem_base + 16384u * 4u;
    const unsigned hB_smem   = smem_base + 32768u * 4u;
    const unsigned mbarA     = smem_base + 51520u * 4u;
    const unsigned mbarB     = mbarA + 8u;

    if (tid == 0) { mbar_init(mbarA, 1); mbar_init(mbarB, 1); }

    // ---- One-time: Wh slice (local c = g*8+jj <-> global g*512 + cg6*8 + jj) ----
    for (int idx = tid; idx < HID * 32; idx += 256) {
        int k = idx >> 5, c = idx & 31;
        Wh_s[idx] = Wh[(size_t)k * 2048 + (c >> 3) * 512 + cg6 * 8 + (c & 7)];
    }
    float wi_r[4], bi_r[4];
    #pragma unroll
    for (int g = 0; g < 4; ++g) {
        wi_r[g] = Wi[g * 512 + cg6 * 8 + j];
        bi_r[g] = bias[g * 512 + cg6 * 8 + j];
    }
    __syncthreads();

    float cstA = 0.f, cstB = 0.f;        // cell state for (b, j) per chain
    const size_t TH = (size_t)TT * HID;

    const int hoff = kh * 8192 + oct * 8 + bh * 4;   // into h buffers
    const int woff = kh * 8192 + c2 * 2;             // into Wh_s

    // One phase of one chain. Exchange (release -> poll -> TMA issue) happens
    // at the tail; the transfer completes during the OTHER chain's phase.
    #define PHASE(HBUF, HSMEM, BG, MBAR, XS, CST)                               \
    do {                                                                        \
        if (t > 0) mbar_wait(MBAR, (unsigned)((t - 1) & 1));                    \
        u64 a00 = 0, a01 = 0, a10 = 0, a11 = 0;                                 \
        if (t > 0) {                                                            \
            const float* hq = HBUF + hoff;                                      \
            const float* wq = Wh_s + woff;                                      \
            _Pragma("unroll 8")                                                 \
            for (int kk = 0; kk < 256; ++kk) {                                  \
                ulonglong2 hv = *(const ulonglong2*)(hq + kk * 32);             \
                float2 w = *(const float2*)(wq + kk * 32);                      \
                u64 W0 = pack2(w.x), W1 = pack2(w.y);                           \
                ffma2(a00, hv.x, W0); ffma2(a01, hv.y, W0);                     \
                ffma2(a10, hv.x, W1); ffma2(a11, hv.y, W1);                     \
            }                                                                   \
        }                                                                       \
        {                                                                       \
            float* zp = z2 + (kh * 32 + 2 * c2) * ZPAD + oct * 8 + bh * 4;      \
            *(u64*)zp = a00; *(u64*)(zp + 2) = a01;                             \
            float* zq = zp + ZPAD;                                              \
            *(u64*)zq = a10; *(u64*)(zq + 2) = a11;                             \
        }                                                                       \
        __syncthreads();                                                        \
        {                                                                       \
            float zs[4];                                                        \
            _Pragma("unroll")                                                   \
            for (int g = 0; g < 4; ++g) {                                       \
                int c = g * 8 + j;                                              \
                zs[g] = z2[c * ZPAD + b] + z2[(32 + c) * ZPAD + b];             \
            }                                                                   \
            float xr = XS[b];                                                   \
            float vi = zs[0] + xr * wi_r[0] + bi_r[0];                          \
            float vf = zs[1] + xr * wi_r[1] + bi_r[1];                          \
            float vg = zs[2] + xr * wi_r[2] + bi_r[2];                          \
            float vo = zs[3] + xr * wi_r[3] + bi_r[3];                          \
            float ig = 1.0f / (1.0f + __expf(-vi));                             \
            float fg = 1.0f / (1.0f + __expf(-vf));                             \
            float eg = __expf(2.0f * vg);                                       \
            float gv = 1.0f - 2.0f / (eg + 1.0f);                               \
            float og = 1.0f / (1.0f + __expf(-vo));                             \
            float cn = fg * (CST) + ig * gv;                                    \
            (CST) = cn;                                                         \
            float ec = __expf(2.0f * cn);                                       \
            float hr = og * (1.0f - 2.0f / (ec + 1.0f));                        \
            out[(size_t)((BG) * 32 + b) * TH + (size_t)t * HID + cg6 * 8 + j] = hr; \
            g_Hbuf[BG][(t + 1) & 1][(cg6 * 8 + j) * 32 + b] = hr;               \
        }                                                                       \
        __syncthreads();                                                        \
        if (tid == 0)                                                           \
            asm volatile("st.release.gpu.global.u32 [%0], %1;"                  \
                         :: "l"(&g_flag[BG][cg6][0]), "r"((unsigned)(t + 1))    \
                         : "memory");                                           \
        if (t < TT - 1) {                                                       \
            if (tid < 32) {                                                     \
                poll_flag(&g_flag[BG][tid][0],      (unsigned)(t + 1));         \
                poll_flag(&g_flag[BG][tid + 32][0], (unsigned)(t + 1));         \
                __syncwarp();                                                   \
                if (tid == 0) {                                                 \
                    const float* src = &g_Hbuf[BG][(t + 1) & 1][0];             \
                    mbar_expect_tx(MBAR, 65536u);                               \
                    bulk_g2s(HSMEM,          src,        32768u, MBAR);         \
                    bulk_g2s(HSMEM + 32768u, src + 8192, 32768u, MBAR);         \
                }                                                               \
            }                                                                   \
        }                                                                       \
    } while (0)

    for (int t = 0; t < TT; ++t) {
        // x for both chains this step (visible to gates via the z2 sync)
        if (tid >= 64 && tid < 96)
            xA_s[tid - 64] = x[(size_t)(bgA * 32 + (tid - 64)) * TT + (TT - 1 - t)];
        else if (tid >= 96 && tid < 128)
            xB_s[tid - 96] = x[(size_t)(bgB * 32 + (tid - 96)) * TT + (TT - 1 - t)];

        PHASE(hA_s, hA_smem, bgA, mbarA, xA_s, cstA);   // A's TMA rides under B
        PHASE(hB_s, hB_smem, bgB, mbarB, xB_s, cstB);   // B's TMA rides under next A
    }
    #undef PHASE
}

extern "C" void kernel_launch(void* const* d_in, const int* in_sizes, int n_in,
                              void* d_out, int out_size)
{
    // inputs: [0]=s (unused), [1]=x (128*2048), [2]=Wi (2048), [3]=Wh (512*2048), [4]=b (2048)
    const float* x    = (const float*)d_in[1];
    const float* Wi   = (const float*)d_in[2];
    const float* Wh   = (const float*)d_in[3];
    const float* bias = (const float*)d_in[4];
    float* out = (float*)d_out;

    size_t smem = (size_t)(51520 + 4) * sizeof(float);   // 206,096 B
    cudaFuncSetAttribute(lstm_persistent_kernel,
                         cudaFuncAttributeMaxDynamicSharedMemorySize, (int)smem);

    lstm_init_kernel<<<1, 256>>>();
    lstm_persistent_kernel<<<128, 256, smem>>>(x, Wi, Wh, bias, out);
}